// round 15
// baseline (speedup 1.0000x reference)
#include <cuda_runtime.h>
#include <cuda_fp16.h>
#include <cstdint>

// ---------------- problem constants ----------------
#define BATCH   4
#define NSEQ    8192
#define CDIM    768
#define HEADS   12
#define DHEAD   64
#define RTOT    (BATCH*NSEQ)      // 32768 rows
#define KVC     1536              // k||v feature dim
#define BHN     (BATCH*HEADS)     // 48
#define SCALE   0.125f            // D^-0.5
#define EPSLN   1e-5f
#define CC      (CDIM*CDIM)
#define NSM_CTAS 296              // 2 CTAs/SM x 148 SMs (persistent grid)

// ---------------- scratch (static device arrays; no runtime malloc) ----------------
__device__ __half g_xnh[RTOT*CDIM];      // layernormed x, fp16 (48 MB)
__device__ __half g_wrh[KVC*CDIM];       // fp16 Wkv, rows reordered per head-pair
__device__ float  g_bkv[KVC];            // kv bias, reordered to match
__device__ __half g_wqth[CC];            // fp16 Wq^T  [c][hd]
__device__ float  g_sumexp[BHN*DHEAD];   // softmax denominators
__device__ float  g_ctx[BHN*DHEAD*DHEAD];// sum exp(k)*v
__device__ __half g_uth[BATCH*CC];       // U^T_b [c3][hd], fp16
__device__ __half g_gth[BATCH*CC];       // Gt_b [c3][c], fp16 (incl. SCALE)
__device__ float  g_beff[BATCH*CDIM];    // folded bias per batch
__device__ float  g_zerob[CDIM];         // zero bias (never written -> stays 0)

__device__ __forceinline__ void cp16(void* s, const void* g) {
    unsigned sa = (unsigned)__cvta_generic_to_shared(s);
    asm volatile("cp.async.cg.shared.global [%0], [%1], 16;\n" :: "r"(sa), "l"(g));
}
__device__ __forceinline__ uint32_t smem_u32(const void* p) {
    uint32_t a;
    asm("{ .reg .u64 t; cvta.to.shared.u64 t, %1; cvt.u32.u64 %0, t; }"
        : "=r"(a) : "l"(p));
    return a;
}
#define LDM4(r0, r1, r2, r3, addr)                                              \
    asm volatile("ldmatrix.sync.aligned.m8n8.x4.shared.b16 {%0,%1,%2,%3}, [%4];"\
                 : "=r"(r0), "=r"(r1), "=r"(r2), "=r"(r3) : "r"(addr))
#define LDM4T(r0, r1, r2, r3, addr)                                             \
    asm volatile("ldmatrix.sync.aligned.m8n8.x4.trans.shared.b16 {%0,%1,%2,%3}, [%4];"\
                 : "=r"(r0), "=r"(r1), "=r"(r2), "=r"(r3) : "r"(addr))
#define MMA16816(c0, c1, c2, c3, a0, a1, a2, a3, b0, b1)                        \
    asm volatile(                                                               \
        "mma.sync.aligned.m16n8k16.row.col.f32.f16.f16.f32 "                   \
        "{%0,%1,%2,%3}, {%4,%5,%6,%7}, {%8,%9}, {%0,%1,%2,%3};\n"              \
        : "+f"(c0), "+f"(c1), "+f"(c2), "+f"(c3)                                \
        : "r"(a0), "r"(a1), "r"(a2), "r"(a3), "r"(b0), "r"(b1))

// ---------------- prep: weight fp16 convert/reorder + accum zero + LayerNorm ----------------
// blocks [0, PREP_RND) do weight prep; blocks [PREP_RND, PREP_RND+RTOT/8) do LN.
#define PREP_RND ((KVC*CDIM + 255) / 256)
__global__ __launch_bounds__(256) void prep_k(const float* __restrict__ w,
                                              const float* __restrict__ qb,
                                              const float* __restrict__ x,
                                              const float* __restrict__ lw,
                                              const float* __restrict__ lb) {
    if (blockIdx.x < PREP_RND) {
        int i = blockIdx.x * blockDim.x + threadIdx.x;
        if (i < KVC*CDIM) {
            int rr = i / CDIM, c = i - rr * CDIM;
            int h = rr >> 7, lr = rr & 127;
            int src = (lr < 64) ? (h * 64 + lr) : (CDIM + h * 64 + lr - 64);
            g_wrh[i] = __float2half_rn(w[CC + (long long)src * CDIM + c]);
            if (c == 0) g_bkv[rr] = qb[CDIM + src];
        }
        if (i < CC) {
            int hd = i / CDIM, c = i - hd * CDIM;
            g_wqth[c * CDIM + hd] = __float2half_rn(w[i]);
        }
        if (i < BHN*DHEAD) g_sumexp[i] = 0.f;
        if (i < BHN*DHEAD*DHEAD) g_ctx[i] = 0.f;
        return;
    }
    // ---- LayerNorm: one warp per row ----
    int t = threadIdx.x, lane = t & 31, wr = t >> 5;
    long long row = (long long)(blockIdx.x - PREP_RND) * 8 + wr;
    const float4* xr = (const float4*)(x + row * CDIM);
    float4 v[6];
    float s = 0.f, ss = 0.f;
    #pragma unroll
    for (int i = 0; i < 6; i++) {
        v[i] = xr[lane + i * 32];
        s  += v[i].x + v[i].y + v[i].z + v[i].w;
        ss += v[i].x*v[i].x + v[i].y*v[i].y + v[i].z*v[i].z + v[i].w*v[i].w;
    }
    #pragma unroll
    for (int o = 16; o; o >>= 1) {
        s  += __shfl_xor_sync(0xffffffffu, s,  o);
        ss += __shfl_xor_sync(0xffffffffu, ss, o);
    }
    float mu   = s * (1.f / CDIM);
    float var  = ss * (1.f / CDIM) - mu * mu;
    float rstd = rsqrtf(var + EPSLN);
    __half2* o = (__half2*)(g_xnh + row * CDIM);
    const float4* wq = (const float4*)lw;
    const float4* bq = (const float4*)lb;
    #pragma unroll
    for (int i = 0; i < 6; i++) {
        int idx = lane + i * 32;
        float4 wv = wq[idx], bv = bq[idx];
        float o0 = (v[i].x - mu) * rstd * wv.x + bv.x;
        float o1 = (v[i].y - mu) * rstd * wv.y + bv.y;
        float o2 = (v[i].z - mu) * rstd * wv.z + bv.z;
        float o3 = (v[i].w - mu) * rstd * wv.w + bv.w;
        o[idx * 2]     = __floats2half2_rn(o0, o1);
        o[idx * 2 + 1] = __floats2half2_rn(o2, o3);
    }
}

// ---------------- FP16 tensor-core GEMM, persistent-CTA tiling ----------------
// A[m][k] row-major half (lda), B[n][k] row-major half (ldb).
// Tiles: ntiles total; decode tile -> (z, by, bx) via tpz (tiles per z) and bxn.
// k-tile 64 halves (128B rows, SW128), 3-stage cp.async, 1 barrier per k64.
// FUSE=false: C[m][n] = alpha * sum + bias[n] (exp on n<expn), OutT out.
// FUSE=true : N-tile = head h = [ek(64)|v(64)]; tail accumulates ctx/sumexp.
#define H_STAGES 3
#define H_STAGE_BYTES 16384                // 128 rows x 128 B
#define H_SMEM_BYTES (2 * H_STAGES * H_STAGE_BYTES)   // 98304

template <typename OutT, bool FUSE>
__global__ __launch_bounds__(256, 2)
void gemm_h(const __half* __restrict__ A, const __half* __restrict__ B,
            const float* __restrict__ bias, OutT* __restrict__ C,
            int K, int lda, int ldb, int ldc, float alpha, int expn,
            long long bsA, long long bsB, long long bsC, int bsBias,
            int ntiles, int tpz, int bxn) {
    extern __shared__ __align__(1024) unsigned char hsm[];
    const uint32_t sbA = smem_u32(hsm);
    const uint32_t sbB = sbA + H_STAGES * H_STAGE_BYTES;

    const int t = threadIdx.x;
    const int lane = t & 31, wid = t >> 5;
    const int wm = (wid >> 2) * 64, wn = (wid & 3) * 32;
    const int grp = lane >> 2, thr = lane & 3;
    const int lr = t >> 1, lcp = (t & 1) << 2;   // 2 threads/row, 4 chunks each

    const int arow = (lane & 15);
    const int brow = (lane & 7) + ((lane >> 4) << 3);
    const int acs  = lane >> 4;
    const int bcs  = (lane >> 3) & 1;
    const int T = K >> 6;   // K / 64

    for (int tile = blockIdx.x; tile < ntiles; tile += gridDim.x) {
        const int z  = tile / tpz;
        const int r  = tile - z * tpz;
        const int by = r / bxn;
        const int bx = r - by * bxn;
        const int n0 = bx * 128, m0 = by * 128;
        const __half* Ab = A + (long long)z * bsA;
        const __half* Bb = B + (long long)z * bsB;
        OutT*         Cb = C + (long long)z * bsC;
        const float* biasb = bias + (long long)z * bsBias;

        float acc[4][4][4];
        #pragma unroll
        for (int i = 0; i < 4; i++)
            #pragma unroll
            for (int j = 0; j < 4; j++)
                #pragma unroll
                for (int q = 0; q < 4; q++) acc[i][j][q] = 0.f;

        #define H_LOAD(slot, k0)                                                \
            do {                                                                \
                _Pragma("unroll")                                               \
                for (int c2 = 0; c2 < 4; c2++) {                                \
                    int ch = lcp + c2;                                          \
                    int sw = lr * 128 + ((ch ^ (lr & 7)) << 4);                 \
                    cp16(hsm + (slot) * H_STAGE_BYTES + sw,                     \
                         Ab + (long long)(m0 + lr) * lda + (k0) + ch * 8);      \
                    cp16(hsm + (H_STAGES + (slot)) * H_STAGE_BYTES + sw,        \
                         Bb + (long long)(n0 + lr) * ldb + (k0) + ch * 8);      \
                }                                                               \
                asm volatile("cp.async.commit_group;\n");                       \
            } while (0)

        H_LOAD(0, 0);
        H_LOAD(1, 64);

        for (int tt = 0; tt < T; tt++) {
            asm volatile("cp.async.wait_group 1;\n" ::: "memory");
            __syncthreads();   // slot-reuse + data-ready ordering
            if (tt + 2 < T) {
                H_LOAD((tt + 2) % H_STAGES, (tt + 2) << 6);
            } else {
                asm volatile("cp.async.commit_group;\n");
            }
            const int slot = tt % H_STAGES;
            const uint32_t aBase = sbA + slot * H_STAGE_BYTES;
            const uint32_t bBase = sbB + slot * H_STAGE_BYTES;
            #pragma unroll
            for (int j = 0; j < 4; j++) {       // four k16 steps per k64 tile
                uint32_t a[4][4], b[2][4];
                #pragma unroll
                for (int mi = 0; mi < 4; mi++) {
                    int row = wm + mi * 16 + arow;
                    int ch = 2 * j + acs;
                    uint32_t ad = aBase + row * 128 + ((ch ^ (row & 7)) << 4);
                    LDM4(a[mi][0], a[mi][1], a[mi][2], a[mi][3], ad);
                }
                #pragma unroll
                for (int njp = 0; njp < 2; njp++) {
                    int row = wn + njp * 16 + brow;
                    int ch = 2 * j + bcs;
                    uint32_t bd = bBase + row * 128 + ((ch ^ (row & 7)) << 4);
                    LDM4(b[njp][0], b[njp][1], b[njp][2], b[njp][3], bd);
                }
                #pragma unroll
                for (int mi = 0; mi < 4; mi++)
                    #pragma unroll
                    for (int nj = 0; nj < 4; nj++)
                        MMA16816(acc[mi][nj][0], acc[mi][nj][1],
                                 acc[mi][nj][2], acc[mi][nj][3],
                                 a[mi][0], a[mi][1], a[mi][2], a[mi][3],
                                 b[nj >> 1][(nj & 1) * 2],
                                 b[nj >> 1][(nj & 1) * 2 + 1]);
            }
        }
        #undef H_LOAD

        // drain all pending cp.async groups before smem reuse / next tile
        asm volatile("cp.async.wait_group 0;\n" ::: "memory");

        if constexpr (!FUSE) {
            const bool doexp = (n0 < expn);
            #pragma unroll
            for (int mi = 0; mi < 4; mi++) {
                #pragma unroll
                for (int nj = 0; nj < 4; nj++) {
                    int m = m0 + wm + mi * 16 + grp;
                    int n = n0 + wn + nj * 8 + 2 * thr;
                    float bi0 = biasb[n], bi1 = biasb[n + 1];
                    float o00 = alpha * acc[mi][nj][0] + bi0;
                    float o01 = alpha * acc[mi][nj][1] + bi1;
                    float o10 = alpha * acc[mi][nj][2] + bi0;
                    float o11 = alpha * acc[mi][nj][3] + bi1;
                    if (doexp) {
                        o00 = __expf(o00); o01 = __expf(o01);
                        o10 = __expf(o10); o11 = __expf(o11);
                    }
                    if constexpr (sizeof(OutT) == 4) {
                        *(float2*)&Cb[(long long)m * ldc + n] = make_float2(o00, o01);
                        *(float2*)&Cb[(long long)(m + 8) * ldc + n] = make_float2(o10, o11);
                    } else {
                        *(__half2*)&Cb[(long long)m * ldc + n] = __floats2half2_rn(o00, o01);
                        *(__half2*)&Cb[(long long)(m + 8) * ldc + n] = __floats2half2_rn(o10, o11);
                    }
                }
            }
        } else {
            // ---- fused ctx tail ----
            __syncthreads();
            {
                const bool isk = (wn < 64);
                unsigned char* basep = hsm + (isk ? 0 : H_STAGE_BYTES);
                #pragma unroll
                for (int mi = 0; mi < 4; mi++) {
                    #pragma unroll
                    for (int nj = 0; nj < 4; nj++) {
                        int m = wm + mi * 16 + grp;              // local row
                        int nloc = wn + nj * 8 + 2 * thr;
                        int n = n0 + nloc;
                        float bi0 = biasb[n], bi1 = biasb[n + 1];
                        float o00 = acc[mi][nj][0] + bi0;
                        float o01 = acc[mi][nj][1] + bi1;
                        float o10 = acc[mi][nj][2] + bi0;
                        float o11 = acc[mi][nj][3] + bi1;
                        if (isk) {
                            o00 = __expf(o00); o01 = __expf(o01);
                            o10 = __expf(o10); o11 = __expf(o11);
                        }
                        int col = isk ? nloc : (nloc - 64);      // 0..63, even
                        int c = col >> 3, off = (col * 2) & 15;
                        int m2 = m + 8;
                        *(__half2*)(basep + m * 128 + ((c ^ (m & 7)) << 4) + off) =
                            __floats2half2_rn(o00, o01);
                        *(__half2*)(basep + m2 * 128 + ((c ^ (m2 & 7)) << 4) + off) =
                            __floats2half2_rn(o10, o11);
                    }
                }
            }
            __syncthreads();
            if (wid < 4) {
                const uint32_t ksb = sbA;
                const uint32_t vsb = sbA + H_STAGE_BYTES;
                const int b = m0 / NSEQ;
                const int bh = b * HEADS + bx;
                const int m0d = wid * 16;                        // d-slice per warp
                float a2[8][4];
                float so[4] = {0.f, 0.f, 0.f, 0.f};
                #pragma unroll
                for (int i = 0; i < 8; i++)
                    #pragma unroll
                    for (int q = 0; q < 4; q++) a2[i][q] = 0.f;

                const int rA = (lane & 7) + ((lane >> 4) << 3);
                const int cA = (m0d >> 3) + ((lane >> 3) & 1);
                const int rB = (lane & 7) + (((lane >> 3) & 1) << 3);
                const uint32_t ones2 = 0x3C003C00u;

                #pragma unroll
                for (int s = 0; s < 8; s++) {
                    int k0 = s * 16;
                    uint32_t a0, a1, a2r, a3;
                    {
                        int r2 = k0 + rA;
                        LDM4T(a0, a1, a2r, a3,
                              ksb + r2 * 128 + ((cA ^ (r2 & 7)) << 4));
                    }
                    uint32_t bf[4][4];
                    #pragma unroll
                    for (int njp = 0; njp < 4; njp++) {
                        int r2 = k0 + rB;
                        int c = njp * 2 + (lane >> 4);
                        LDM4T(bf[njp][0], bf[njp][1], bf[njp][2], bf[njp][3],
                              vsb + r2 * 128 + ((c ^ (r2 & 7)) << 4));
                    }
                    #pragma unroll
                    for (int nj = 0; nj < 8; nj++)
                        MMA16816(a2[nj][0], a2[nj][1], a2[nj][2], a2[nj][3],
                                 a0, a1, a2r, a3,
                                 bf[nj >> 1][(nj & 1) * 2],
                                 bf[nj >> 1][(nj & 1) * 2 + 1]);
                    MMA16816(so[0], so[1], so[2], so[3], a0, a1, a2r, a3,
                             ones2, ones2);
                }
                float* cb = &g_ctx[bh * 4096];
                #pragma unroll
                for (int nj = 0; nj < 8; nj++) {
                    int e = nj * 8 + 2 * thr;
                    atomicAdd(&cb[(m0d + grp) * 64 + e],     a2[nj][0]);
                    atomicAdd(&cb[(m0d + grp) * 64 + e + 1], a2[nj][1]);
                    atomicAdd(&cb[(m0d + grp + 8) * 64 + e],     a2[nj][2]);
                    atomicAdd(&cb[(m0d + grp + 8) * 64 + e + 1], a2[nj][3]);
                }
                if (thr == 0) {
                    atomicAdd(&g_sumexp[bh * 64 + m0d + grp],     so[0]);
                    atomicAdd(&g_sumexp[bh * 64 + m0d + grp + 8], so[2]);
                }
            }
        }
        __syncthreads();   // all warps done with smem before next tile's loads
    }
}

// ---------------- U^T_b[c3][h*64+d] = sum_e (ctx[d,e]/sumexp[d]) * proj_w[c3, h*64+e] ----------------
__global__ __launch_bounds__(256) void u_k(const float* __restrict__ pw) {
    int bh = blockIdx.x;
    int c30 = blockIdx.y * 64;
    int b = bh / HEADS, h = bh - b * HEADS;
    int t = threadIdx.x;
    __shared__ float inv[64];
    __shared__ float sce[64][68];  // [e][d]
    __shared__ float spw[64][68];  // [e][c3_local]
    if (t < 64) inv[t] = 1.f / g_sumexp[bh * 64 + t];
    __syncthreads();
    #pragma unroll
    for (int i = 0; i < 16; i++) {
        int idx = t + i * 256;
        int d = idx >> 6, e = idx & 63;
        sce[e][d] = g_ctx[bh * 4096 + idx] * inv[d];
    }
    #pragma unroll
    for (int i = 0; i < 16; i++) {
        int idx = t + i * 256;
        int c3l = idx >> 6, e = idx & 63;
        spw[e][c3l] = pw[(long long)(c30 + c3l) * CDIM + h * 64 + e];
    }
    __syncthreads();
    int d0 = (t & 15) * 4, c0 = (t >> 4) * 4;
    float acc[4][4];
    #pragma unroll
    for (int i = 0; i < 4; i++)
        #pragma unroll
        for (int j = 0; j < 4; j++) acc[i][j] = 0.f;
    #pragma unroll 8
    for (int e = 0; e < 64; e++) {
        float4 a  = *(float4*)&sce[e][d0];
        float4 bb = *(float4*)&spw[e][c0];
        float av[4] = {a.x, a.y, a.z, a.w};
        float bv[4] = {bb.x, bb.y, bb.z, bb.w};
        #pragma unroll
        for (int i = 0; i < 4; i++)
            #pragma unroll
            for (int j = 0; j < 4; j++) acc[i][j] += av[i] * bv[j];
    }
    __half* Ut = &g_uth[(long long)b * CC];
    #pragma unroll
    for (int i = 0; i < 4; i++)
        #pragma unroll
        for (int j = 0; j < 4; j++)
            Ut[(long long)(c30 + c0 + j) * CDIM + h * 64 + d0 + i] =
                __float2half_rn(acc[i][j]);
}

// ---------------- b_eff[b][c3] = scale * sum_hd qkv_b[hd]*U^T[c3][hd] + proj_b[c3] ----------------
__global__ __launch_bounds__(256) void beff_k(const float* __restrict__ qb,
                                              const float* __restrict__ pb) {
    int b = blockIdx.x;
    int c3 = blockIdx.y * 256 + threadIdx.x;
    const __half* Ut = &g_uth[(long long)b * CC + (long long)c3 * CDIM];
    float acc = pb[c3];
    #pragma unroll 8
    for (int hd = 0; hd < CDIM; hd++)
        acc += SCALE * qb[hd] * __half2float(Ut[hd]);
    g_beff[b * CDIM + c3] = acc;
}

// ---------------- launch ----------------
extern "C" void kernel_launch(void* const* d_in, const int* in_sizes, int n_in,
                              void* d_out, int out_size) {
    const float* x      = (const float*)d_in[0];
    const float* ln_w   = (const float*)d_in[1];
    const float* ln_b   = (const float*)d_in[2];
    const float* qkv_w  = (const float*)d_in[3];
    const float* qkv_b  = (const float*)d_in[4];
    const float* proj_w = (const float*)d_in[5];
    const float* proj_b = (const float*)d_in[6];
    float* out = (float*)d_out;

    static __half* xnh_p = nullptr;
    static __half* wrh_p = nullptr;
    static float*  bkv_p = nullptr;
    static __half* wqth_p = nullptr;
    static __half* uth_p = nullptr;
    static __half* gth_p = nullptr;
    static float*  beff_p = nullptr;
    static float*  zerob_p = nullptr;
    if (!xnh_p) {
        cudaGetSymbolAddress((void**)&xnh_p, g_xnh);
        cudaGetSymbolAddress((void**)&wrh_p, g_wrh);
        cudaGetSymbolAddress((void**)&bkv_p, g_bkv);
        cudaGetSymbolAddress((void**)&wqth_p, g_wqth);
        cudaGetSymbolAddress((void**)&uth_p, g_uth);
        cudaGetSymbolAddress((void**)&gth_p, g_gth);
        cudaGetSymbolAddress((void**)&beff_p, g_beff);
        cudaGetSymbolAddress((void**)&zerob_p, g_zerob);
        cudaFuncSetAttribute((const void*)gemm_h<__half, true>,
                             cudaFuncAttributeMaxDynamicSharedMemorySize,
                             H_SMEM_BYTES);
        cudaFuncSetAttribute((const void*)gemm_h<__half, false>,
                             cudaFuncAttributeMaxDynamicSharedMemorySize,
                             H_SMEM_BYTES);
        cudaFuncSetAttribute((const void*)gemm_h<float, false>,
                             cudaFuncAttributeMaxDynamicSharedMemorySize,
                             H_SMEM_BYTES);
    }

    // 1. prep: weight fp16 reorder + accumulator zero + LayerNorm (merged)
    prep_k<<<PREP_RND + RTOT / 8, 256>>>(qkv_w, qkv_b, x, ln_w, ln_b);
    // 2. FUSED: per-head [ek|v] projection + ctx/sumexp (persistent CTAs)
    //    tiles: bx = head (12), by = row-chunk (256); ntiles 3072
    gemm_h<__half, true><<<NSM_CTAS, 256, H_SMEM_BYTES>>>(
        xnh_p, wrh_p, bkv_p, (__half*)nullptr,
        CDIM, CDIM, CDIM, 0, 1.f, 0, 0, 0, 0, 0,
        HEADS * (RTOT / 128), HEADS * (RTOT / 128), HEADS);
    // 3. U^T_b (fp16) = blockdiag(ctx_norm) applied to proj_w
    u_k<<<dim3(BHN, CDIM / 64), 256>>>(proj_w);
    // 4. effective bias
    beff_k<<<dim3(BATCH, CDIM / 256), 256>>>(qkv_b, proj_b);
    // 5. Gt_b[c3][c] = SCALE * U^T_b @ Wq  (36 tiles/batch, 144 total)
    gemm_h<__half, false><<<144, 256, H_SMEM_BYTES>>>(
        uth_p, wqth_p, zerob_p, gth_p,
        CDIM, CDIM, CDIM, CDIM, SCALE, 0,
        (long long)CC, 0, (long long)CC, 0,
        144, 36, CDIM / 128);
    // 6. final = xn[b] @ Gt_b^T + b_eff[b]  (persistent CTAs; 1536 tiles)
    gemm_h<float, false><<<NSM_CTAS, 256, H_SMEM_BYTES>>>(
        xnh_p, gth_p, beff_p, out,
        CDIM, CDIM, CDIM, CDIM, 1.f, 0,
        (long long)NSEQ * CDIM, (long long)CC,
        (long long)NSEQ * CDIM, CDIM,
        (CDIM / 128) * (NSEQ / 128) * BATCH, (CDIM / 128) * (NSEQ / 128),
        CDIM / 128);
}

// round 16
// speedup vs baseline: 1.3234x; 1.3234x over previous
#include <cuda_runtime.h>
#include <cuda_fp16.h>
#include <cstdint>

// ---------------- problem constants ----------------
#define BATCH   4
#define NSEQ    8192
#define CDIM    768
#define HEADS   12
#define DHEAD   64
#define RTOT    (BATCH*NSEQ)      // 32768 rows
#define KVC     1536              // k||v feature dim
#define BHN     (BATCH*HEADS)     // 48
#define SCALE   0.125f            // D^-0.5
#define EPSLN   1e-5f
#define CC      (CDIM*CDIM)

// ---------------- scratch (static device arrays; no runtime malloc) ----------------
__device__ __half g_xnh[RTOT*CDIM];      // layernormed x, fp16 (48 MB)
__device__ __half g_wrh[KVC*CDIM];       // fp16 Wkv, rows reordered per head-pair
__device__ float  g_bkv[KVC];            // kv bias, reordered to match
__device__ __half g_wqth[CC];            // fp16 Wq^T  [c][hd]
__device__ float  g_sumexp[BHN*DHEAD];   // softmax denominators
__device__ float  g_ctx[BHN*DHEAD*DHEAD];// sum exp(k)*v
__device__ __half g_uth[BATCH*CC];       // U^T_b [c3][hd], fp16
__device__ __half g_gth[BATCH*CC];       // Gt_b [c3][c], fp16 (incl. SCALE)
__device__ float  g_beff[BATCH*CDIM];    // folded bias per batch
__device__ float  g_zerob[CDIM];         // zero bias (never written -> stays 0)

__device__ __forceinline__ void cp16(void* s, const void* g) {
    unsigned sa = (unsigned)__cvta_generic_to_shared(s);
    asm volatile("cp.async.cg.shared.global [%0], [%1], 16;\n" :: "r"(sa), "l"(g));
}
__device__ __forceinline__ uint32_t smem_u32(const void* p) {
    uint32_t a;
    asm("{ .reg .u64 t; cvta.to.shared.u64 t, %1; cvt.u32.u64 %0, t; }"
        : "=r"(a) : "l"(p));
    return a;
}
#define LDM4(r0, r1, r2, r3, addr)                                              \
    asm volatile("ldmatrix.sync.aligned.m8n8.x4.shared.b16 {%0,%1,%2,%3}, [%4];"\
                 : "=r"(r0), "=r"(r1), "=r"(r2), "=r"(r3) : "r"(addr))
#define LDM4T(r0, r1, r2, r3, addr)                                             \
    asm volatile("ldmatrix.sync.aligned.m8n8.x4.trans.shared.b16 {%0,%1,%2,%3}, [%4];"\
                 : "=r"(r0), "=r"(r1), "=r"(r2), "=r"(r3) : "r"(addr))
#define MMA16816(c0, c1, c2, c3, a0, a1, a2, a3, b0, b1)                        \
    asm volatile(                                                               \
        "mma.sync.aligned.m16n8k16.row.col.f32.f16.f16.f32 "                   \
        "{%0,%1,%2,%3}, {%4,%5,%6,%7}, {%8,%9}, {%0,%1,%2,%3};\n"              \
        : "+f"(c0), "+f"(c1), "+f"(c2), "+f"(c3)                                \
        : "r"(a0), "r"(a1), "r"(a2), "r"(a3), "r"(b0), "r"(b1))

// ---------------- prep: weight fp16 convert/reorder + accum zero + LayerNorm ----------------
#define PREP_RND ((KVC*CDIM + 255) / 256)
__global__ __launch_bounds__(256) void prep_k(const float* __restrict__ w,
                                              const float* __restrict__ qb,
                                              const float* __restrict__ x,
                                              const float* __restrict__ lw,
                                              const float* __restrict__ lb) {
    if (blockIdx.x < PREP_RND) {
        int i = blockIdx.x * blockDim.x + threadIdx.x;
        if (i < KVC*CDIM) {
            int rr = i / CDIM, c = i - rr * CDIM;
            int h = rr >> 7, lr = rr & 127;
            int src = (lr < 64) ? (h * 64 + lr) : (CDIM + h * 64 + lr - 64);
            g_wrh[i] = __float2half_rn(w[CC + (long long)src * CDIM + c]);
            if (c == 0) g_bkv[rr] = qb[CDIM + src];
        }
        if (i < CC) {
            int hd = i / CDIM, c = i - hd * CDIM;
            g_wqth[c * CDIM + hd] = __float2half_rn(w[i]);
        }
        if (i < BHN*DHEAD) g_sumexp[i] = 0.f;
        if (i < BHN*DHEAD*DHEAD) g_ctx[i] = 0.f;
        return;
    }
    // ---- LayerNorm: one warp per row ----
    int t = threadIdx.x, lane = t & 31, wr = t >> 5;
    long long row = (long long)(blockIdx.x - PREP_RND) * 8 + wr;
    const float4* xr = (const float4*)(x + row * CDIM);
    float4 v[6];
    float s = 0.f, ss = 0.f;
    #pragma unroll
    for (int i = 0; i < 6; i++) {
        v[i] = xr[lane + i * 32];
        s  += v[i].x + v[i].y + v[i].z + v[i].w;
        ss += v[i].x*v[i].x + v[i].y*v[i].y + v[i].z*v[i].z + v[i].w*v[i].w;
    }
    #pragma unroll
    for (int o = 16; o; o >>= 1) {
        s  += __shfl_xor_sync(0xffffffffu, s,  o);
        ss += __shfl_xor_sync(0xffffffffu, ss, o);
    }
    float mu   = s * (1.f / CDIM);
    float var  = ss * (1.f / CDIM) - mu * mu;
    float rstd = rsqrtf(var + EPSLN);
    __half2* o = (__half2*)(g_xnh + row * CDIM);
    const float4* wq = (const float4*)lw;
    const float4* bq = (const float4*)lb;
    #pragma unroll
    for (int i = 0; i < 6; i++) {
        int idx = lane + i * 32;
        float4 wv = wq[idx], bv = bq[idx];
        float o0 = (v[i].x - mu) * rstd * wv.x + bv.x;
        float o1 = (v[i].y - mu) * rstd * wv.y + bv.y;
        float o2 = (v[i].z - mu) * rstd * wv.z + bv.z;
        float o3 = (v[i].w - mu) * rstd * wv.w + bv.w;
        o[idx * 2]     = __floats2half2_rn(o0, o1);
        o[idx * 2 + 1] = __floats2half2_rn(o2, o3);
    }
}

// ---------------- FP16 tensor-core GEMM (round-14 form: discrete grid) ----------------
// A[m][k] row-major half (lda), B[n][k] row-major half (ldb).
// k-tile 64 halves (128B rows, full SW128 swizzle), 3-stage cp.async pipeline,
// single barrier per k64 iteration.
// FUSE=false: C[m][n] = alpha * sum + bias[n] (exp on n<expn), OutT out.
// FUSE=true : N-tile = head h = [ek(64) | v(64)]; epilogue applies exp to the
//             ek half, stages ek/v in smem, then warps 0-3 compute
//             ctx[bh][d][e] += sum_n ek[n,d] v[n,e] and sumexp via MMA.
#define H_STAGES 3
#define H_STAGE_BYTES 16384                // 128 rows x 128 B
#define H_SMEM_BYTES (2 * H_STAGES * H_STAGE_BYTES)   // 98304

template <typename OutT, bool FUSE>
__global__ __launch_bounds__(256, 2)
void gemm_h(const __half* __restrict__ A, const __half* __restrict__ B,
            const float* __restrict__ bias, OutT* __restrict__ C,
            int K, int lda, int ldb, int ldc, float alpha, int expn,
            long long bsA, long long bsB, long long bsC, int bsBias) {
    extern __shared__ __align__(1024) unsigned char hsm[];
    const uint32_t sbA = smem_u32(hsm);
    const uint32_t sbB = sbA + H_STAGES * H_STAGE_BYTES;

    const int t = threadIdx.x;
    const int lane = t & 31, wid = t >> 5;
    const int n0 = blockIdx.x * 128, m0 = blockIdx.y * 128;
    const __half* Ab = A + (long long)blockIdx.z * bsA;
    const __half* Bb = B + (long long)blockIdx.z * bsB;
    OutT*         Cb = C + (long long)blockIdx.z * bsC;
    const float* biasb = bias + (long long)blockIdx.z * bsBias;

    const int wm = (wid >> 2) * 64, wn = (wid & 3) * 32;
    const int grp = lane >> 2, thr = lane & 3;
    const int lr = t >> 1, lcp = (t & 1) << 2;   // 2 threads/row, 4 chunks each

    float acc[4][4][4];
    #pragma unroll
    for (int i = 0; i < 4; i++)
        #pragma unroll
        for (int j = 0; j < 4; j++)
            #pragma unroll
            for (int q = 0; q < 4; q++) acc[i][j][q] = 0.f;

    #define H_LOAD(slot, k0)                                                    \
        do {                                                                    \
            _Pragma("unroll")                                                   \
            for (int c2 = 0; c2 < 4; c2++) {                                    \
                int ch = lcp + c2;                                              \
                int sw = lr * 128 + ((ch ^ (lr & 7)) << 4);                     \
                cp16(hsm + (slot) * H_STAGE_BYTES + sw,                         \
                     Ab + (long long)(m0 + lr) * lda + (k0) + ch * 8);          \
                cp16(hsm + (H_STAGES + (slot)) * H_STAGE_BYTES + sw,            \
                     Bb + (long long)(n0 + lr) * ldb + (k0) + ch * 8);          \
            }                                                                   \
            asm volatile("cp.async.commit_group;\n");                           \
        } while (0)

    const int T = K >> 6;   // K / 64
    H_LOAD(0, 0);
    H_LOAD(1, 64);

    const int arow = (lane & 15);
    const int brow = (lane & 7) + ((lane >> 4) << 3);
    const int acs  = lane >> 4;
    const int bcs  = (lane >> 3) & 1;

    for (int tt = 0; tt < T; tt++) {
        asm volatile("cp.async.wait_group 1;\n" ::: "memory");
        __syncthreads();   // single barrier: slot-reuse + data-ready ordering
        if (tt + 2 < T) {
            H_LOAD((tt + 2) % H_STAGES, (tt + 2) << 6);
        } else {
            asm volatile("cp.async.commit_group;\n");
        }
        const int slot = tt % H_STAGES;
        const uint32_t aBase = sbA + slot * H_STAGE_BYTES;
        const uint32_t bBase = sbB + slot * H_STAGE_BYTES;
        #pragma unroll
        for (int j = 0; j < 4; j++) {           // four k16 steps per k64 tile
            uint32_t a[4][4], b[2][4];
            #pragma unroll
            for (int mi = 0; mi < 4; mi++) {
                int row = wm + mi * 16 + arow;
                int ch = 2 * j + acs;
                uint32_t ad = aBase + row * 128 + ((ch ^ (row & 7)) << 4);
                LDM4(a[mi][0], a[mi][1], a[mi][2], a[mi][3], ad);
            }
            #pragma unroll
            for (int njp = 0; njp < 2; njp++) {
                int row = wn + njp * 16 + brow;
                int ch = 2 * j + bcs;
                uint32_t bd = bBase + row * 128 + ((ch ^ (row & 7)) << 4);
                LDM4(b[njp][0], b[njp][1], b[njp][2], b[njp][3], bd);
            }
            #pragma unroll
            for (int mi = 0; mi < 4; mi++)
                #pragma unroll
                for (int nj = 0; nj < 4; nj++)
                    MMA16816(acc[mi][nj][0], acc[mi][nj][1],
                             acc[mi][nj][2], acc[mi][nj][3],
                             a[mi][0], a[mi][1], a[mi][2], a[mi][3],
                             b[nj >> 1][(nj & 1) * 2],
                             b[nj >> 1][(nj & 1) * 2 + 1]);
        }
    }
    #undef H_LOAD

    if constexpr (!FUSE) {
        const bool doexp = (n0 < expn);
        #pragma unroll
        for (int mi = 0; mi < 4; mi++) {
            #pragma unroll
            for (int nj = 0; nj < 4; nj++) {
                int m = m0 + wm + mi * 16 + grp;
                int n = n0 + wn + nj * 8 + 2 * thr;
                float bi0 = biasb[n], bi1 = biasb[n + 1];
                float o00 = alpha * acc[mi][nj][0] + bi0;
                float o01 = alpha * acc[mi][nj][1] + bi1;
                float o10 = alpha * acc[mi][nj][2] + bi0;
                float o11 = alpha * acc[mi][nj][3] + bi1;
                if (doexp) {
                    o00 = __expf(o00); o01 = __expf(o01);
                    o10 = __expf(o10); o11 = __expf(o11);
                }
                if constexpr (sizeof(OutT) == 4) {
                    *(float2*)&Cb[(long long)m * ldc + n] = make_float2(o00, o01);
                    *(float2*)&Cb[(long long)(m + 8) * ldc + n] = make_float2(o10, o11);
                } else {
                    *(__half2*)&Cb[(long long)m * ldc + n] = __floats2half2_rn(o00, o01);
                    *(__half2*)&Cb[(long long)(m + 8) * ldc + n] = __floats2half2_rn(o10, o11);
                }
            }
        }
    } else {
        // ---- fused ctx tail ----
        asm volatile("cp.async.wait_group 0;\n" ::: "memory");
        __syncthreads();
        {
            const bool isk = (wn < 64);
            unsigned char* basep = hsm + (isk ? 0 : H_STAGE_BYTES);
            #pragma unroll
            for (int mi = 0; mi < 4; mi++) {
                #pragma unroll
                for (int nj = 0; nj < 4; nj++) {
                    int m = wm + mi * 16 + grp;              // local row
                    int nloc = wn + nj * 8 + 2 * thr;
                    int n = n0 + nloc;
                    float bi0 = biasb[n], bi1 = biasb[n + 1];
                    float o00 = acc[mi][nj][0] + bi0;
                    float o01 = acc[mi][nj][1] + bi1;
                    float o10 = acc[mi][nj][2] + bi0;
                    float o11 = acc[mi][nj][3] + bi1;
                    if (isk) {
                        o00 = __expf(o00); o01 = __expf(o01);
                        o10 = __expf(o10); o11 = __expf(o11);
                    }
                    int col = isk ? nloc : (nloc - 64);      // 0..63, even
                    int c = col >> 3, off = (col * 2) & 15;
                    int m2 = m + 8;
                    *(__half2*)(basep + m * 128 + ((c ^ (m & 7)) << 4) + off) =
                        __floats2half2_rn(o00, o01);
                    *(__half2*)(basep + m2 * 128 + ((c ^ (m2 & 7)) << 4) + off) =
                        __floats2half2_rn(o10, o11);
                }
            }
        }
        __syncthreads();
        if (wid < 4) {
            const uint32_t ksb = sbA;
            const uint32_t vsb = sbA + H_STAGE_BYTES;
            const int b = m0 / NSEQ;
            const int bh = b * HEADS + blockIdx.x;
            const int m0d = wid * 16;                        // d-slice per warp
            float a2[8][4];
            float so[4] = {0.f, 0.f, 0.f, 0.f};
            #pragma unroll
            for (int i = 0; i < 8; i++)
                #pragma unroll
                for (int q = 0; q < 4; q++) a2[i][q] = 0.f;

            const int rA = (lane & 7) + ((lane >> 4) << 3);
            const int cA = (m0d >> 3) + ((lane >> 3) & 1);
            const int rB = (lane & 7) + (((lane >> 3) & 1) << 3);
            const uint32_t ones2 = 0x3C003C00u;

            #pragma unroll
            for (int s = 0; s < 8; s++) {
                int k0 = s * 16;
                uint32_t a0, a1, a2r, a3;
                {
                    int r = k0 + rA;
                    LDM4T(a0, a1, a2r, a3, ksb + r * 128 + ((cA ^ (r & 7)) << 4));
                }
                uint32_t bf[4][4];
                #pragma unroll
                for (int njp = 0; njp < 4; njp++) {
                    int r = k0 + rB;
                    int c = njp * 2 + (lane >> 4);
                    LDM4T(bf[njp][0], bf[njp][1], bf[njp][2], bf[njp][3],
                          vsb + r * 128 + ((c ^ (r & 7)) << 4));
                }
                #pragma unroll
                for (int nj = 0; nj < 8; nj++)
                    MMA16816(a2[nj][0], a2[nj][1], a2[nj][2], a2[nj][3],
                             a0, a1, a2r, a3,
                             bf[nj >> 1][(nj & 1) * 2], bf[nj >> 1][(nj & 1) * 2 + 1]);
                MMA16816(so[0], so[1], so[2], so[3], a0, a1, a2r, a3, ones2, ones2);
            }
            float* cb = &g_ctx[bh * 4096];
            #pragma unroll
            for (int nj = 0; nj < 8; nj++) {
                int e = nj * 8 + 2 * thr;
                atomicAdd(&cb[(m0d + grp) * 64 + e],     a2[nj][0]);
                atomicAdd(&cb[(m0d + grp) * 64 + e + 1], a2[nj][1]);
                atomicAdd(&cb[(m0d + grp + 8) * 64 + e],     a2[nj][2]);
                atomicAdd(&cb[(m0d + grp + 8) * 64 + e + 1], a2[nj][3]);
            }
            if (thr == 0) {
                atomicAdd(&g_sumexp[bh * 64 + m0d + grp],     so[0]);
                atomicAdd(&g_sumexp[bh * 64 + m0d + grp + 8], so[2]);
            }
        }
    }
}

// ---------------- U^T_b[c3][h*64+d] = sum_e (ctx[d,e]/sumexp[d]) * proj_w[c3, h*64+e] ----------------
__global__ __launch_bounds__(256) void u_k(const float* __restrict__ pw) {
    int bh = blockIdx.x;
    int c30 = blockIdx.y * 64;
    int b = bh / HEADS, h = bh - b * HEADS;
    int t = threadIdx.x;
    __shared__ float inv[64];
    __shared__ float sce[64][68];  // [e][d]
    __shared__ float spw[64][68];  // [e][c3_local]
    if (t < 64) inv[t] = 1.f / g_sumexp[bh * 64 + t];
    __syncthreads();
    #pragma unroll
    for (int i = 0; i < 16; i++) {
        int idx = t + i * 256;
        int d = idx >> 6, e = idx & 63;
        sce[e][d] = g_ctx[bh * 4096 + idx] * inv[d];
    }
    #pragma unroll
    for (int i = 0; i < 16; i++) {
        int idx = t + i * 256;
        int c3l = idx >> 6, e = idx & 63;
        spw[e][c3l] = pw[(long long)(c30 + c3l) * CDIM + h * 64 + e];
    }
    __syncthreads();
    int d0 = (t & 15) * 4, c0 = (t >> 4) * 4;
    float acc[4][4];
    #pragma unroll
    for (int i = 0; i < 4; i++)
        #pragma unroll
        for (int j = 0; j < 4; j++) acc[i][j] = 0.f;
    #pragma unroll 8
    for (int e = 0; e < 64; e++) {
        float4 a  = *(float4*)&sce[e][d0];
        float4 bb = *(float4*)&spw[e][c0];
        float av[4] = {a.x, a.y, a.z, a.w};
        float bv[4] = {bb.x, bb.y, bb.z, bb.w};
        #pragma unroll
        for (int i = 0; i < 4; i++)
            #pragma unroll
            for (int j = 0; j < 4; j++) acc[i][j] += av[i] * bv[j];
    }
    __half* Ut = &g_uth[(long long)b * CC];
    #pragma unroll
    for (int i = 0; i < 4; i++)
        #pragma unroll
        for (int j = 0; j < 4; j++)
            Ut[(long long)(c30 + c0 + j) * CDIM + h * 64 + d0 + i] =
                __float2half_rn(acc[i][j]);
}

// ---------------- b_eff: warp-per-output dot product ----------------
// beff[b][c3] = SCALE * sum_hd qb[hd] * U^T[c3][hd] + pb[c3]
__global__ __launch_bounds__(256) void beff_k(const float* __restrict__ qb,
                                              const float* __restrict__ pb) {
    int gw = (blockIdx.x * 256 + threadIdx.x) >> 5;   // global warp id, 0..3071
    int lane = threadIdx.x & 31;
    int b = gw / CDIM, c3 = gw - b * CDIM;
    const __half2* Ut2 =
        (const __half2*)&g_uth[(long long)b * CC + (long long)c3 * CDIM];
    const float2* qb2 = (const float2*)qb;
    float acc = 0.f;
    #pragma unroll
    for (int i = lane; i < CDIM / 2; i += 32) {
        float2 q = qb2[i];
        float2 u = __half22float2(Ut2[i]);
        acc += q.x * u.x + q.y * u.y;
    }
    #pragma unroll
    for (int o = 16; o; o >>= 1)
        acc += __shfl_xor_sync(0xffffffffu, acc, o);
    if (lane == 0) g_beff[b * CDIM + c3] = SCALE * acc + pb[c3];
}

// ---------------- launch ----------------
extern "C" void kernel_launch(void* const* d_in, const int* in_sizes, int n_in,
                              void* d_out, int out_size) {
    const float* x      = (const float*)d_in[0];
    const float* ln_w   = (const float*)d_in[1];
    const float* ln_b   = (const float*)d_in[2];
    const float* qkv_w  = (const float*)d_in[3];
    const float* qkv_b  = (const float*)d_in[4];
    const float* proj_w = (const float*)d_in[5];
    const float* proj_b = (const float*)d_in[6];
    float* out = (float*)d_out;

    static __half* xnh_p = nullptr;
    static __half* wrh_p = nullptr;
    static float*  bkv_p = nullptr;
    static __half* wqth_p = nullptr;
    static __half* uth_p = nullptr;
    static __half* gth_p = nullptr;
    static float*  beff_p = nullptr;
    static float*  zerob_p = nullptr;
    if (!xnh_p) {
        cudaGetSymbolAddress((void**)&xnh_p, g_xnh);
        cudaGetSymbolAddress((void**)&wrh_p, g_wrh);
        cudaGetSymbolAddress((void**)&bkv_p, g_bkv);
        cudaGetSymbolAddress((void**)&wqth_p, g_wqth);
        cudaGetSymbolAddress((void**)&uth_p, g_uth);
        cudaGetSymbolAddress((void**)&gth_p, g_gth);
        cudaGetSymbolAddress((void**)&beff_p, g_beff);
        cudaGetSymbolAddress((void**)&zerob_p, g_zerob);
        cudaFuncSetAttribute((const void*)gemm_h<__half, true>,
                             cudaFuncAttributeMaxDynamicSharedMemorySize,
                             H_SMEM_BYTES);
        cudaFuncSetAttribute((const void*)gemm_h<__half, false>,
                             cudaFuncAttributeMaxDynamicSharedMemorySize,
                             H_SMEM_BYTES);
        cudaFuncSetAttribute((const void*)gemm_h<float, false>,
                             cudaFuncAttributeMaxDynamicSharedMemorySize,
                             H_SMEM_BYTES);
    }

    // 1. prep: weight fp16 reorder + accumulator zero + LayerNorm (merged)
    prep_k<<<PREP_RND + RTOT / 8, 256>>>(qkv_w, qkv_b, x, ln_w, ln_b);
    // 2. FUSED: per-head [ek|v] projection + ctx/sumexp accumulation
    gemm_h<__half, true><<<dim3(HEADS, RTOT / 128, 1), 256, H_SMEM_BYTES>>>(
        xnh_p, wrh_p, bkv_p, (__half*)nullptr,
        CDIM, CDIM, CDIM, 0, 1.f, 0, 0, 0, 0, 0);
    // 3. U^T_b (fp16) = blockdiag(ctx_norm) applied to proj_w
    u_k<<<dim3(BHN, CDIM / 64), 256>>>(proj_w);
    // 4. effective bias (warp-per-output)
    beff_k<<<BATCH * CDIM / 8, 256>>>(qkv_b, proj_b);
    // 5. Gt_b[c3][c] = SCALE * U^T_b @ Wq  (fp16 tensor cores)
    gemm_h<__half, false><<<dim3(CDIM / 128, CDIM / 128, BATCH), 256, H_SMEM_BYTES>>>(
        uth_p, wqth_p, zerob_p, gth_p,
        CDIM, CDIM, CDIM, CDIM, SCALE, 0,
        (long long)CC, 0, (long long)CC, 0);
    // 6. final = xn[b] @ Gt_b^T + b_eff[b]   (fp16 tensor cores, fp32 output)
    gemm_h<float, false><<<dim3(CDIM / 128, NSEQ / 128, BATCH), 256, H_SMEM_BYTES>>>(
        xnh_p, gth_p, beff_p, out,
        CDIM, CDIM, CDIM, CDIM, 1.f, 0,
        (long long)NSEQ * CDIM, (long long)CC,
        (long long)NSEQ * CDIM, CDIM);
}

// round 17
// speedup vs baseline: 1.3286x; 1.0039x over previous
#include <cuda_runtime.h>
#include <cuda_fp16.h>
#include <cstdint>

// ---------------- problem constants ----------------
#define BATCH   4
#define NSEQ    8192
#define CDIM    768
#define HEADS   12
#define DHEAD   64
#define RTOT    (BATCH*NSEQ)      // 32768 rows
#define KVC     1536              // k||v feature dim
#define BHN     (BATCH*HEADS)     // 48
#define SCALE   0.125f            // D^-0.5
#define EPSLN   1e-5f
#define CC      (CDIM*CDIM)

// ---------------- scratch (static device arrays; no runtime malloc) ----------------
__device__ __half g_xnh[RTOT*CDIM];      // layernormed x, fp16 (48 MB)
__device__ __half g_wrh[KVC*CDIM];       // fp16 Wkv, rows reordered per head-pair
__device__ float  g_bkv[KVC];            // kv bias, reordered to match
__device__ __half g_wqth[CC];            // fp16 Wq^T  [c][hd]
__device__ float  g_sumexp[BHN*DHEAD];   // softmax denominators
__device__ float  g_ctx[BHN*DHEAD*DHEAD];// sum exp(k)*v
__device__ __half g_uth[BATCH*CC];       // U^T_b [c3][hd], fp16
__device__ __half g_gth[BATCH*CC];       // Gt_b [c3][c], fp16 (incl. SCALE)
__device__ float  g_beff[BATCH*CDIM];    // folded bias per batch
__device__ float  g_zerob[CDIM];         // zero bias (never written -> stays 0)

__device__ __forceinline__ void cp16(void* s, const void* g) {
    unsigned sa = (unsigned)__cvta_generic_to_shared(s);
    asm volatile("cp.async.cg.shared.global [%0], [%1], 16;\n" :: "r"(sa), "l"(g));
}
__device__ __forceinline__ uint32_t smem_u32(const void* p) {
    uint32_t a;
    asm("{ .reg .u64 t; cvta.to.shared.u64 t, %1; cvt.u32.u64 %0, t; }"
        : "=r"(a) : "l"(p));
    return a;
}
#define LDM4(r0, r1, r2, r3, addr)                                              \
    asm volatile("ldmatrix.sync.aligned.m8n8.x4.shared.b16 {%0,%1,%2,%3}, [%4];"\
                 : "=r"(r0), "=r"(r1), "=r"(r2), "=r"(r3) : "r"(addr))
#define LDM4T(r0, r1, r2, r3, addr)                                             \
    asm volatile("ldmatrix.sync.aligned.m8n8.x4.trans.shared.b16 {%0,%1,%2,%3}, [%4];"\
                 : "=r"(r0), "=r"(r1), "=r"(r2), "=r"(r3) : "r"(addr))
#define MMA16816(c0, c1, c2, c3, a0, a1, a2, a3, b0, b1)                        \
    asm volatile(                                                               \
        "mma.sync.aligned.m16n8k16.row.col.f32.f16.f16.f32 "                   \
        "{%0,%1,%2,%3}, {%4,%5,%6,%7}, {%8,%9}, {%0,%1,%2,%3};\n"              \
        : "+f"(c0), "+f"(c1), "+f"(c2), "+f"(c3)                                \
        : "r"(a0), "r"(a1), "r"(a2), "r"(a3), "r"(b0), "r"(b1))

// ---------------- prep: weight fp16 convert/reorder + accum zero + beff init + LayerNorm ----------------
#define PREP_RND ((KVC*CDIM + 255) / 256)
__global__ __launch_bounds__(256) void prep_k(const float* __restrict__ w,
                                              const float* __restrict__ qb,
                                              const float* __restrict__ pb,
                                              const float* __restrict__ x,
                                              const float* __restrict__ lw,
                                              const float* __restrict__ lb) {
    if (blockIdx.x < PREP_RND) {
        int i = blockIdx.x * blockDim.x + threadIdx.x;
        if (i < KVC*CDIM) {
            int rr = i / CDIM, c = i - rr * CDIM;
            int h = rr >> 7, lr = rr & 127;
            int src = (lr < 64) ? (h * 64 + lr) : (CDIM + h * 64 + lr - 64);
            g_wrh[i] = __float2half_rn(w[CC + (long long)src * CDIM + c]);
            if (c == 0) g_bkv[rr] = qb[CDIM + src];
        }
        if (i < CC) {
            int hd = i / CDIM, c = i - hd * CDIM;
            g_wqth[c * CDIM + hd] = __float2half_rn(w[i]);
        }
        if (i < BHN*DHEAD) g_sumexp[i] = 0.f;
        if (i < BHN*DHEAD*DHEAD) g_ctx[i] = 0.f;
        if (i < BATCH*CDIM) g_beff[i] = pb[i % CDIM];
        return;
    }
    // ---- LayerNorm: one warp per row ----
    int t = threadIdx.x, lane = t & 31, wr = t >> 5;
    long long row = (long long)(blockIdx.x - PREP_RND) * 8 + wr;
    const float4* xr = (const float4*)(x + row * CDIM);
    float4 v[6];
    float s = 0.f, ss = 0.f;
    #pragma unroll
    for (int i = 0; i < 6; i++) {
        v[i] = xr[lane + i * 32];
        s  += v[i].x + v[i].y + v[i].z + v[i].w;
        ss += v[i].x*v[i].x + v[i].y*v[i].y + v[i].z*v[i].z + v[i].w*v[i].w;
    }
    #pragma unroll
    for (int o = 16; o; o >>= 1) {
        s  += __shfl_xor_sync(0xffffffffu, s,  o);
        ss += __shfl_xor_sync(0xffffffffu, ss, o);
    }
    float mu   = s * (1.f / CDIM);
    float var  = ss * (1.f / CDIM) - mu * mu;
    float rstd = rsqrtf(var + EPSLN);
    __half2* o = (__half2*)(g_xnh + row * CDIM);
    const float4* wq = (const float4*)lw;
    const float4* bq = (const float4*)lb;
    #pragma unroll
    for (int i = 0; i < 6; i++) {
        int idx = lane + i * 32;
        float4 wv = wq[idx], bv = bq[idx];
        float o0 = (v[i].x - mu) * rstd * wv.x + bv.x;
        float o1 = (v[i].y - mu) * rstd * wv.y + bv.y;
        float o2 = (v[i].z - mu) * rstd * wv.z + bv.z;
        float o3 = (v[i].w - mu) * rstd * wv.w + bv.w;
        o[idx * 2]     = __floats2half2_rn(o0, o1);
        o[idx * 2 + 1] = __floats2half2_rn(o2, o3);
    }
}

// ---------------- FP16 tensor-core GEMM (discrete grid) ----------------
// A[m][k] row-major half (lda), B[n][k] row-major half (ldb).
// k-tile 64 halves (128B rows, full SW128 swizzle), 3-stage cp.async pipeline,
// single barrier per k64 iteration.
// FUSE=false: C[m][n] = alpha * sum + bias[n] (exp on n<expn), OutT out.
// FUSE=true : N-tile = head h = [ek(64) | v(64)]; epilogue applies exp to the
//             ek half, stages ek/v in smem, then warps 0-3 compute
//             ctx[bh][d][e] += sum_n ek[n,d] v[n,e] and sumexp via MMA.
#define H_STAGES 3
#define H_STAGE_BYTES 16384                // 128 rows x 128 B
#define H_SMEM_BYTES (2 * H_STAGES * H_STAGE_BYTES)   // 98304

template <typename OutT, bool FUSE>
__global__ __launch_bounds__(256, 2)
void gemm_h(const __half* __restrict__ A, const __half* __restrict__ B,
            const float* __restrict__ bias, OutT* __restrict__ C,
            int K, int lda, int ldb, int ldc, float alpha, int expn,
            long long bsA, long long bsB, long long bsC, int bsBias) {
    extern __shared__ __align__(1024) unsigned char hsm[];
    const uint32_t sbA = smem_u32(hsm);
    const uint32_t sbB = sbA + H_STAGES * H_STAGE_BYTES;

    const int t = threadIdx.x;
    const int lane = t & 31, wid = t >> 5;
    const int n0 = blockIdx.x * 128, m0 = blockIdx.y * 128;
    const __half* Ab = A + (long long)blockIdx.z * bsA;
    const __half* Bb = B + (long long)blockIdx.z * bsB;
    OutT*         Cb = C + (long long)blockIdx.z * bsC;
    const float* biasb = bias + (long long)blockIdx.z * bsBias;

    const int wm = (wid >> 2) * 64, wn = (wid & 3) * 32;
    const int grp = lane >> 2, thr = lane & 3;
    const int lr = t >> 1, lcp = (t & 1) << 2;   // 2 threads/row, 4 chunks each

    float acc[4][4][4];
    #pragma unroll
    for (int i = 0; i < 4; i++)
        #pragma unroll
        for (int j = 0; j < 4; j++)
            #pragma unroll
            for (int q = 0; q < 4; q++) acc[i][j][q] = 0.f;

    #define H_LOAD(slot, k0)                                                    \
        do {                                                                    \
            _Pragma("unroll")                                                   \
            for (int c2 = 0; c2 < 4; c2++) {                                    \
                int ch = lcp + c2;                                              \
                int sw = lr * 128 + ((ch ^ (lr & 7)) << 4);                     \
                cp16(hsm + (slot) * H_STAGE_BYTES + sw,                         \
                     Ab + (long long)(m0 + lr) * lda + (k0) + ch * 8);          \
                cp16(hsm + (H_STAGES + (slot)) * H_STAGE_BYTES + sw,            \
                     Bb + (long long)(n0 + lr) * ldb + (k0) + ch * 8);          \
            }                                                                   \
            asm volatile("cp.async.commit_group;\n");                           \
        } while (0)

    const int T = K >> 6;   // K / 64
    H_LOAD(0, 0);
    H_LOAD(1, 64);

    const int arow = (lane & 15);
    const int brow = (lane & 7) + ((lane >> 4) << 3);
    const int acs  = lane >> 4;
    const int bcs  = (lane >> 3) & 1;

    for (int tt = 0; tt < T; tt++) {
        asm volatile("cp.async.wait_group 1;\n" ::: "memory");
        __syncthreads();   // single barrier: slot-reuse + data-ready ordering
        if (tt + 2 < T) {
            H_LOAD((tt + 2) % H_STAGES, (tt + 2) << 6);
        } else {
            asm volatile("cp.async.commit_group;\n");
        }
        const int slot = tt % H_STAGES;
        const uint32_t aBase = sbA + slot * H_STAGE_BYTES;
        const uint32_t bBase = sbB + slot * H_STAGE_BYTES;
        #pragma unroll
        for (int j = 0; j < 4; j++) {           // four k16 steps per k64 tile
            uint32_t a[4][4], b[2][4];
            #pragma unroll
            for (int mi = 0; mi < 4; mi++) {
                int row = wm + mi * 16 + arow;
                int ch = 2 * j + acs;
                uint32_t ad = aBase + row * 128 + ((ch ^ (row & 7)) << 4);
                LDM4(a[mi][0], a[mi][1], a[mi][2], a[mi][3], ad);
            }
            #pragma unroll
            for (int njp = 0; njp < 2; njp++) {
                int row = wn + njp * 16 + brow;
                int ch = 2 * j + bcs;
                uint32_t bd = bBase + row * 128 + ((ch ^ (row & 7)) << 4);
                LDM4(b[njp][0], b[njp][1], b[njp][2], b[njp][3], bd);
            }
            #pragma unroll
            for (int mi = 0; mi < 4; mi++)
                #pragma unroll
                for (int nj = 0; nj < 4; nj++)
                    MMA16816(acc[mi][nj][0], acc[mi][nj][1],
                             acc[mi][nj][2], acc[mi][nj][3],
                             a[mi][0], a[mi][1], a[mi][2], a[mi][3],
                             b[nj >> 1][(nj & 1) * 2],
                             b[nj >> 1][(nj & 1) * 2 + 1]);
        }
    }
    #undef H_LOAD

    if constexpr (!FUSE) {
        const bool doexp = (n0 < expn);
        #pragma unroll
        for (int mi = 0; mi < 4; mi++) {
            #pragma unroll
            for (int nj = 0; nj < 4; nj++) {
                int m = m0 + wm + mi * 16 + grp;
                int n = n0 + wn + nj * 8 + 2 * thr;
                float bi0 = biasb[n], bi1 = biasb[n + 1];
                float o00 = alpha * acc[mi][nj][0] + bi0;
                float o01 = alpha * acc[mi][nj][1] + bi1;
                float o10 = alpha * acc[mi][nj][2] + bi0;
                float o11 = alpha * acc[mi][nj][3] + bi1;
                if (doexp) {
                    o00 = __expf(o00); o01 = __expf(o01);
                    o10 = __expf(o10); o11 = __expf(o11);
                }
                if constexpr (sizeof(OutT) == 4) {
                    *(float2*)&Cb[(long long)m * ldc + n] = make_float2(o00, o01);
                    *(float2*)&Cb[(long long)(m + 8) * ldc + n] = make_float2(o10, o11);
                } else {
                    *(__half2*)&Cb[(long long)m * ldc + n] = __floats2half2_rn(o00, o01);
                    *(__half2*)&Cb[(long long)(m + 8) * ldc + n] = __floats2half2_rn(o10, o11);
                }
            }
        }
    } else {
        // ---- fused ctx tail ----
        asm volatile("cp.async.wait_group 0;\n" ::: "memory");
        __syncthreads();
        {
            const bool isk = (wn < 64);
            unsigned char* basep = hsm + (isk ? 0 : H_STAGE_BYTES);
            #pragma unroll
            for (int mi = 0; mi < 4; mi++) {
                #pragma unroll
                for (int nj = 0; nj < 4; nj++) {
                    int m = wm + mi * 16 + grp;              // local row
                    int nloc = wn + nj * 8 + 2 * thr;
                    int n = n0 + nloc;
                    float bi0 = biasb[n], bi1 = biasb[n + 1];
                    float o00 = acc[mi][nj][0] + bi0;
                    float o01 = acc[mi][nj][1] + bi1;
                    float o10 = acc[mi][nj][2] + bi0;
                    float o11 = acc[mi][nj][3] + bi1;
                    if (isk) {
                        o00 = __expf(o00); o01 = __expf(o01);
                        o10 = __expf(o10); o11 = __expf(o11);
                    }
                    int col = isk ? nloc : (nloc - 64);      // 0..63, even
                    int c = col >> 3, off = (col * 2) & 15;
                    int m2 = m + 8;
                    *(__half2*)(basep + m * 128 + ((c ^ (m & 7)) << 4) + off) =
                        __floats2half2_rn(o00, o01);
                    *(__half2*)(basep + m2 * 128 + ((c ^ (m2 & 7)) << 4) + off) =
                        __floats2half2_rn(o10, o11);
                }
            }
        }
        __syncthreads();
        if (wid < 4) {
            const uint32_t ksb = sbA;
            const uint32_t vsb = sbA + H_STAGE_BYTES;
            const int b = m0 / NSEQ;
            const int bh = b * HEADS + blockIdx.x;
            const int m0d = wid * 16;                        // d-slice per warp
            float a2[8][4];
            float so[4] = {0.f, 0.f, 0.f, 0.f};
            #pragma unroll
            for (int i = 0; i < 8; i++)
                #pragma unroll
                for (int q = 0; q < 4; q++) a2[i][q] = 0.f;

            const int rA = (lane & 7) + ((lane >> 4) << 3);
            const int cA = (m0d >> 3) + ((lane >> 3) & 1);
            const int rB = (lane & 7) + (((lane >> 3) & 1) << 3);
            const uint32_t ones2 = 0x3C003C00u;

            #pragma unroll
            for (int s = 0; s < 8; s++) {
                int k0 = s * 16;
                uint32_t a0, a1, a2r, a3;
                {
                    int r = k0 + rA;
                    LDM4T(a0, a1, a2r, a3, ksb + r * 128 + ((cA ^ (r & 7)) << 4));
                }
                uint32_t bf[4][4];
                #pragma unroll
                for (int njp = 0; njp < 4; njp++) {
                    int r = k0 + rB;
                    int c = njp * 2 + (lane >> 4);
                    LDM4T(bf[njp][0], bf[njp][1], bf[njp][2], bf[njp][3],
                          vsb + r * 128 + ((c ^ (r & 7)) << 4));
                }
                #pragma unroll
                for (int nj = 0; nj < 8; nj++)
                    MMA16816(a2[nj][0], a2[nj][1], a2[nj][2], a2[nj][3],
                             a0, a1, a2r, a3,
                             bf[nj >> 1][(nj & 1) * 2], bf[nj >> 1][(nj & 1) * 2 + 1]);
                MMA16816(so[0], so[1], so[2], so[3], a0, a1, a2r, a3, ones2, ones2);
            }
            float* cb = &g_ctx[bh * 4096];
            #pragma unroll
            for (int nj = 0; nj < 8; nj++) {
                int e = nj * 8 + 2 * thr;
                atomicAdd(&cb[(m0d + grp) * 64 + e],     a2[nj][0]);
                atomicAdd(&cb[(m0d + grp) * 64 + e + 1], a2[nj][1]);
                atomicAdd(&cb[(m0d + grp + 8) * 64 + e],     a2[nj][2]);
                atomicAdd(&cb[(m0d + grp + 8) * 64 + e + 1], a2[nj][3]);
            }
            if (thr == 0) {
                atomicAdd(&g_sumexp[bh * 64 + m0d + grp],     so[0]);
                atomicAdd(&g_sumexp[bh * 64 + m0d + grp + 8], so[2]);
            }
        }
    }
}

// ---------------- U^T + fused beff contribution ----------------
// U^T_b[c3][h*64+d] = sum_e (ctx[d,e]/sumexp[d]) * proj_w[c3, h*64+e]
// beff[b][c3] += SCALE * sum_d qb[h*64+d] * U^T_b[c3][h*64+d]  (atomic)
__global__ __launch_bounds__(256) void u_k(const float* __restrict__ pw,
                                           const float* __restrict__ qb) {
    int bh = blockIdx.x;
    int c30 = blockIdx.y * 64;
    int b = bh / HEADS, h = bh - b * HEADS;
    int t = threadIdx.x;
    __shared__ float inv[64];
    __shared__ float sce[64][68];  // [e][d]
    __shared__ float spw[64][68];  // [e][c3_local]
    if (t < 64) inv[t] = 1.f / g_sumexp[bh * 64 + t];
    __syncthreads();
    #pragma unroll
    for (int i = 0; i < 16; i++) {
        int idx = t + i * 256;
        int d = idx >> 6, e = idx & 63;
        sce[e][d] = g_ctx[bh * 4096 + idx] * inv[d];
    }
    #pragma unroll
    for (int i = 0; i < 16; i++) {
        int idx = t + i * 256;
        int c3l = idx >> 6, e = idx & 63;
        spw[e][c3l] = pw[(long long)(c30 + c3l) * CDIM + h * 64 + e];
    }
    __syncthreads();
    int d0 = (t & 15) * 4, c0 = (t >> 4) * 4;
    float acc[4][4];
    #pragma unroll
    for (int i = 0; i < 4; i++)
        #pragma unroll
        for (int j = 0; j < 4; j++) acc[i][j] = 0.f;
    #pragma unroll 8
    for (int e = 0; e < 64; e++) {
        float4 a  = *(float4*)&sce[e][d0];
        float4 bb = *(float4*)&spw[e][c0];
        float av[4] = {a.x, a.y, a.z, a.w};
        float bv[4] = {bb.x, bb.y, bb.z, bb.w};
        #pragma unroll
        for (int i = 0; i < 4; i++)
            #pragma unroll
            for (int j = 0; j < 4; j++) acc[i][j] += av[i] * bv[j];
    }
    __half* Ut = &g_uth[(long long)b * CC];
    #pragma unroll
    for (int i = 0; i < 4; i++)
        #pragma unroll
        for (int j = 0; j < 4; j++)
            Ut[(long long)(c30 + c0 + j) * CDIM + h * 64 + d0 + i] =
                __float2half_rn(acc[i][j]);
    // ---- fused beff contribution ----
    float qv[4];
    #pragma unroll
    for (int i = 0; i < 4; i++) qv[i] = qb[h * 64 + d0 + i];
    #pragma unroll
    for (int j = 0; j < 4; j++) {
        float p = qv[0]*acc[0][j] + qv[1]*acc[1][j] + qv[2]*acc[2][j] + qv[3]*acc[3][j];
        #pragma unroll
        for (int o = 8; o; o >>= 1)
            p += __shfl_xor_sync(0xffffffffu, p, o);
        if ((t & 15) == 0)
            atomicAdd(&g_beff[b * CDIM + c30 + c0 + j], SCALE * p);
    }
}

// ---------------- launch ----------------
extern "C" void kernel_launch(void* const* d_in, const int* in_sizes, int n_in,
                              void* d_out, int out_size) {
    const float* x      = (const float*)d_in[0];
    const float* ln_w   = (const float*)d_in[1];
    const float* ln_b   = (const float*)d_in[2];
    const float* qkv_w  = (const float*)d_in[3];
    const float* qkv_b  = (const float*)d_in[4];
    const float* proj_w = (const float*)d_in[5];
    const float* proj_b = (const float*)d_in[6];
    float* out = (float*)d_out;

    static __half* xnh_p = nullptr;
    static __half* wrh_p = nullptr;
    static float*  bkv_p = nullptr;
    static __half* wqth_p = nullptr;
    static __half* uth_p = nullptr;
    static __half* gth_p = nullptr;
    static float*  beff_p = nullptr;
    static float*  zerob_p = nullptr;
    if (!xnh_p) {
        cudaGetSymbolAddress((void**)&xnh_p, g_xnh);
        cudaGetSymbolAddress((void**)&wrh_p, g_wrh);
        cudaGetSymbolAddress((void**)&bkv_p, g_bkv);
        cudaGetSymbolAddress((void**)&wqth_p, g_wqth);
        cudaGetSymbolAddress((void**)&uth_p, g_uth);
        cudaGetSymbolAddress((void**)&gth_p, g_gth);
        cudaGetSymbolAddress((void**)&beff_p, g_beff);
        cudaGetSymbolAddress((void**)&zerob_p, g_zerob);
        cudaFuncSetAttribute((const void*)gemm_h<__half, true>,
                             cudaFuncAttributeMaxDynamicSharedMemorySize,
                             H_SMEM_BYTES);
        cudaFuncSetAttribute((const void*)gemm_h<__half, false>,
                             cudaFuncAttributeMaxDynamicSharedMemorySize,
                             H_SMEM_BYTES);
        cudaFuncSetAttribute((const void*)gemm_h<float, false>,
                             cudaFuncAttributeMaxDynamicSharedMemorySize,
                             H_SMEM_BYTES);
    }

    // 1. prep: weight fp16 reorder + accumulator zero + beff init + LayerNorm
    prep_k<<<PREP_RND + RTOT / 8, 256>>>(qkv_w, qkv_b, proj_b, x, ln_w, ln_b);
    // 2. FUSED: per-head [ek|v] projection + ctx/sumexp accumulation
    gemm_h<__half, true><<<dim3(HEADS, RTOT / 128, 1), 256, H_SMEM_BYTES>>>(
        xnh_p, wrh_p, bkv_p, (__half*)nullptr,
        CDIM, CDIM, CDIM, 0, 1.f, 0, 0, 0, 0, 0);
    // 3. U^T_b (fp16) + fused beff accumulation
    u_k<<<dim3(BHN, CDIM / 64), 256>>>(proj_w, qkv_b);
    // 4. Gt_b[c3][c] = SCALE * U^T_b @ Wq  (fp16 tensor cores)
    gemm_h<__half, false><<<dim3(CDIM / 128, CDIM / 128, BATCH), 256, H_SMEM_BYTES>>>(
        uth_p, wqth_p, zerob_p, gth_p,
        CDIM, CDIM, CDIM, CDIM, SCALE, 0,
        (long long)CC, 0, (long long)CC, 0);
    // 5. final = xn[b] @ Gt_b^T + b_eff[b]   (fp16 tensor cores, fp32 output)
    gemm_h<float, false><<<dim3(CDIM / 128, NSEQ / 128, BATCH), 256, H_SMEM_BYTES>>>(
        xnh_p, gth_p, beff_p, out,
        CDIM, CDIM, CDIM, CDIM, 1.f, 0,
        (long long)NSEQ * CDIM, (long long)CC,
        (long long)NSEQ * CDIM, CDIM);
}